// round 6
// baseline (speedup 1.0000x reference)
#include <cuda_runtime.h>
#include <math.h>

#define NUM_USERS 8192
#define ROW 1000
#define TOP_K 10
#define THREADS 256
#define WPB (THREADS / 32)   // warps (users) per block

__global__ __launch_bounds__(THREADS)
void metric_kernel(const float4* __restrict__ lg4,   // 2 logit-pairs per float4
                   const int4*   __restrict__ dup4,  // 4 dup flags per int4
                   float* __restrict__ out) {
    const int lane = threadIdx.x & 31;
    const int user = blockIdx.x * WPB + (threadIdx.x >> 5);

    const float BIG_NEG = -3.402823466e38f;  // finfo(float32).min

    const long F = (long)user * (ROW / 2);   // 500 float4 per user
    const long D = (long)user * (ROW / 4);   // 250 int4  per user

    // unit u_k = lane + 32k (k = 0..7); unit u covers elements [4u, 4u+4)
    // 3-deep register pipeline: slots hold units k, k+1, k+2
    int4 d[3]; float4 a[3], b[3];

    #pragma unroll
    for (int s = 0; s < 3; s++) {
        const int u = lane + 32 * s;             // <= 95 < 250, always valid
        d[s] = __ldcs(&dup4[D + u]);
        a[s] = __ldcs(&lg4[F + 2 * u]);
        b[s] = __ldcs(&lg4[F + 2 * u + 1]);
    }

    // element 0 lives in lane 0's unit 0: dup = d[0].x, logit = a[0].y
    const float l0c = (d[0].x != 0) ? BIG_NEG : a[0].y;
    const float l0  = __shfl_sync(0xFFFFFFFFu, l0c, 0);

    int pack = 0;   // (cnt << 16) | dsum ; both sums <= 1000, no carry

    #pragma unroll
    for (int k = 0; k < 8; k++) {
        const int s = k % 3;

        // snapshot current unit, then refill slot with unit k+3
        const int4   dd = d[s];
        const float4 aa = a[s];
        const float4 bb = b[s];

        if (k < 5) {
            const int u = lane + 32 * (k + 3);
            if (u < (ROW / 4)) {
                d[s] = __ldcs(&dup4[D + u]);
                a[s] = __ldcs(&lg4[F + 2 * u]);
                b[s] = __ldcs(&lg4[F + 2 * u + 1]);
            } else {
                // neutral: dup=0 (dsum+=0), logits=BIG_NEG (never > l0)
                d[s] = make_int4(0, 0, 0, 0);
                a[s] = make_float4(0.f, BIG_NEG, 0.f, BIG_NEG);
                b[s] = a[s];
            }
        }

        const float v0 = (dd.x != 0) ? BIG_NEG : aa.y;
        const float v1 = (dd.y != 0) ? BIG_NEG : aa.w;
        const float v2 = (dd.z != 0) ? BIG_NEG : bb.y;
        const float v3 = (dd.w != 0) ? BIG_NEG : bb.w;

        const int c = (v0 > l0) + (v1 > l0) + (v2 > l0) + (v3 > l0);
        pack += (c << 16) + (dd.x + dd.y + dd.z + dd.w);
    }

    // packed warp reduction — 5 shuffles total, no smem, no barriers
    #pragma unroll
    for (int o = 16; o > 0; o >>= 1)
        pack += __shfl_down_sync(0xFFFFFFFFu, pack, o);

    if (lane == 0) {
        const int cnt  = pack >> 16;
        const int dsum = pack & 0xFFFF;

        float pos    = (float)cnt;
        float intop  = (pos < (float)TOP_K) ? 1.0f : 0.0f;
        float ndcg   = intop * (0.6931471805599453f / logf(pos + 2.0f));
        float weight = (dsum != (ROW - 1)) ? 1.0f : 0.0f;

        out[user]                 = intop;
        out[NUM_USERS + user]     = ndcg;
        out[2 * NUM_USERS + user] = weight;
    }
}

extern "C" void kernel_launch(void* const* d_in, const int* in_sizes, int n_in,
                              void* d_out, int out_size) {
    const float4* lg4  = (const float4*)d_in[0];
    const int4*   dup4 = (const int4*)d_in[1];
    float*        out  = (float*)d_out;

    metric_kernel<<<NUM_USERS / WPB, THREADS>>>(lg4, dup4, out);
}

// round 7
// speedup vs baseline: 1.3609x; 1.3609x over previous
#include <cuda_runtime.h>
#include <math.h>

#define NUM_USERS 8192
#define ROW 1000
#define TOP_K 10
#define THREADS 256
#define WPB (THREADS / 32)   // warps (users) per block

__global__ __launch_bounds__(THREADS)
void metric_kernel(const float4* __restrict__ lg4,   // 2 logit-pairs per float4
                   const int4*   __restrict__ dup4,  // 4 dup flags per int4
                   float* __restrict__ out) {
    const int lane = threadIdx.x & 31;
    const int user = blockIdx.x * WPB + (threadIdx.x >> 5);

    const float BIG_NEG = -3.402823466e38f;  // finfo(float32).min

    const long F = (long)user * (ROW / 2);   // 500 float4 per user
    const long D = (long)user * (ROW / 4);   // 250 int4  per user

    // unit u_k = lane + 32k (k = 0..7); unit u covers elements [4u, 4u+4)
    // 2-deep register pipeline; default cache policy -> inputs stay L2-resident
    int4 d, nd; float4 a, b, na, nb;

    d  = dup4[D + lane];
    a  = lg4[F + 2 * lane];
    b  = lg4[F + 2 * lane + 1];
    nd = dup4[D + lane + 32];
    na = lg4[F + 2 * (lane + 32)];
    nb = lg4[F + 2 * (lane + 32) + 1];

    // element 0 lives in lane 0's unit 0: dup = d.x, logit = a.y
    const float l0c = (d.x != 0) ? BIG_NEG : a.y;
    const float l0  = __shfl_sync(0xFFFFFFFFu, l0c, 0);

    int pack = 0;   // (cnt << 16) | dsum ; both sums <= 1000, no carry

    #pragma unroll
    for (int k = 0; k < 8; k++) {
        // prefetch unit k+2 while consuming unit k
        int4 pd; float4 pa, pb;
        if (k < 6) {
            const int u = lane + 32 * (k + 2);
            if (u < (ROW / 4)) {
                pd = dup4[D + u];
                pa = lg4[F + 2 * u];
                pb = lg4[F + 2 * u + 1];
            } else {
                // neutral: dup=0 (dsum+=0), logits=BIG_NEG (never > l0)
                pd = make_int4(0, 0, 0, 0);
                pa = make_float4(0.f, BIG_NEG, 0.f, BIG_NEG);
                pb = pa;
            }
        }

        const float v0 = (d.x != 0) ? BIG_NEG : a.y;
        const float v1 = (d.y != 0) ? BIG_NEG : a.w;
        const float v2 = (d.z != 0) ? BIG_NEG : b.y;
        const float v3 = (d.w != 0) ? BIG_NEG : b.w;

        const int c = (v0 > l0) + (v1 > l0) + (v2 > l0) + (v3 > l0);
        pack += (c << 16) + (d.x + d.y + d.z + d.w);

        d = nd; a = na; b = nb;
        if (k < 6) { nd = pd; na = pa; nb = pb; }
    }

    // packed warp reduction — 5 shuffles, no smem, no barriers
    #pragma unroll
    for (int o = 16; o > 0; o >>= 1)
        pack += __shfl_down_sync(0xFFFFFFFFu, pack, o);

    if (lane == 0) {
        const int cnt  = pack >> 16;
        const int dsum = pack & 0xFFFF;

        float pos    = (float)cnt;
        float intop  = (pos < (float)TOP_K) ? 1.0f : 0.0f;
        float ndcg   = intop * (0.6931471805599453f / logf(pos + 2.0f));
        float weight = (dsum != (ROW - 1)) ? 1.0f : 0.0f;

        out[user]                 = intop;
        out[NUM_USERS + user]     = ndcg;
        out[2 * NUM_USERS + user] = weight;
    }
}

extern "C" void kernel_launch(void* const* d_in, const int* in_sizes, int n_in,
                              void* d_out, int out_size) {
    const float4* lg4  = (const float4*)d_in[0];
    const int4*   dup4 = (const int4*)d_in[1];
    float*        out  = (float*)d_out;

    metric_kernel<<<NUM_USERS / WPB, THREADS>>>(lg4, dup4, out);
}

// round 8
// speedup vs baseline: 1.3874x; 1.0195x over previous
#include <cuda_runtime.h>
#include <math.h>

#define NUM_USERS 8192
#define ROW 1000
#define TOP_K 10
#define THREADS 64
#define WPB (THREADS / 32)   // warps (users) per block = 2

__global__ __launch_bounds__(THREADS)
void metric_kernel(const float4* __restrict__ lg4,   // 2 logit-pairs per float4
                   const int4*   __restrict__ dup4,  // 4 dup flags per int4
                   float* __restrict__ out) {
    const int lane = threadIdx.x & 31;
    const int user = blockIdx.x * WPB + (threadIdx.x >> 5);

    const float BIG_NEG = -3.402823466e38f;  // finfo(float32).min

    const long F = (long)user * (ROW / 2);   // 500 float4 per user
    const long D = (long)user * (ROW / 4);   // 250 int4  per user

    // unit u_k = lane + 32k (k = 0..7); unit u covers elements [4u, 4u+4)
    // 2-deep register pipeline; default cache policy -> inputs stay L2-resident
    int4 d, nd; float4 a, b, na, nb;

    d  = dup4[D + lane];
    a  = lg4[F + 2 * lane];
    b  = lg4[F + 2 * lane + 1];
    nd = dup4[D + lane + 32];
    na = lg4[F + 2 * (lane + 32)];
    nb = lg4[F + 2 * (lane + 32) + 1];

    // element 0 lives in lane 0's unit 0: dup = d.x, logit = a.y
    const float l0c = (d.x != 0) ? BIG_NEG : a.y;
    const float l0  = __shfl_sync(0xFFFFFFFFu, l0c, 0);

    int pack = 0;   // (cnt << 16) | dsum ; both sums <= 1000, no carry

    #pragma unroll
    for (int k = 0; k < 8; k++) {
        // prefetch unit k+2 while consuming unit k
        int4 pd; float4 pa, pb;
        if (k < 6) {
            const int u = lane + 32 * (k + 2);
            if (u < (ROW / 4)) {
                pd = dup4[D + u];
                pa = lg4[F + 2 * u];
                pb = lg4[F + 2 * u + 1];
            } else {
                // neutral: dup=0 (dsum+=0), logits=BIG_NEG (never > l0)
                pd = make_int4(0, 0, 0, 0);
                pa = make_float4(0.f, BIG_NEG, 0.f, BIG_NEG);
                pb = pa;
            }
        }

        const float v0 = (d.x != 0) ? BIG_NEG : a.y;
        const float v1 = (d.y != 0) ? BIG_NEG : a.w;
        const float v2 = (d.z != 0) ? BIG_NEG : b.y;
        const float v3 = (d.w != 0) ? BIG_NEG : b.w;

        const int c = (v0 > l0) + (v1 > l0) + (v2 > l0) + (v3 > l0);
        pack += (c << 16) + (d.x + d.y + d.z + d.w);

        d = nd; a = na; b = nb;
        if (k < 6) { nd = pd; na = pa; nb = pb; }
    }

    // packed warp reduction — 5 shuffles, no smem, no barriers
    #pragma unroll
    for (int o = 16; o > 0; o >>= 1)
        pack += __shfl_down_sync(0xFFFFFFFFu, pack, o);

    if (lane == 0) {
        const int cnt  = pack >> 16;
        const int dsum = pack & 0xFFFF;

        float pos    = (float)cnt;
        float intop  = (pos < (float)TOP_K) ? 1.0f : 0.0f;
        float ndcg   = intop * (0.6931471805599453f / logf(pos + 2.0f));
        float weight = (dsum != (ROW - 1)) ? 1.0f : 0.0f;

        out[user]                 = intop;
        out[NUM_USERS + user]     = ndcg;
        out[2 * NUM_USERS + user] = weight;
    }
}

extern "C" void kernel_launch(void* const* d_in, const int* in_sizes, int n_in,
                              void* d_out, int out_size) {
    const float4* lg4  = (const float4*)d_in[0];
    const int4*   dup4 = (const int4*)d_in[1];
    float*        out  = (float*)d_out;

    metric_kernel<<<NUM_USERS / WPB, THREADS>>>(lg4, dup4, out);
}